// round 12
// baseline (speedup 1.0000x reference)
#include <cuda_runtime.h>

#define R_GAS   8.3144621f
#define F_CONST 96487.0f
#define ALPHA   0.5f
#define SN_C    0.000437545f
#define SP_C    0.00030962f
#define KN_C    2120.96f
#define KP_C    248898.0f
#define RO_C    0.117215f
#define T_O     6.08671f
#define T_SN    1001.38f
#define T_SP    46.4311f
#define U0P     4.03f
#define U0N     0.01f
#define Q_MAX   (7600.0f / 0.6f)
#define VOL     2e-05f
#define VOL_S   (0.1f * VOL)
#define VOL_B   (VOL - VOL_S)
#define Q_S_MAX (Q_MAX * VOL_S / VOL)
#define LN2_F   0.69314718055994531f

#define INV_QSMAX  (1.0f / Q_S_MAX)
#define INV_VOLB   (1.0f / VOL_B)
#define INV_VOLS   (1.0f / VOL_S)
#define T_DIFF_    7000000.0f
#define INV_TDIFF  (1.0f / T_DIFF_)
#define INV_TSN    (1.0f / T_SN)
#define INV_TSP    (1.0f / T_SP)
#define RTF_LN2    (R_GAS / F_CONST * LN2_F)
#define RTFA_LN2   (R_GAS / F_CONST / ALPHA * LN2_F)
#define CN_C       (1.0f / (SN_C * 2.0f * KN_C))
#define CP_C       (1.0f / (SP_C * 2.0f * KP_C))
#define AN0_F      (86.19f / F_CONST)

// Leaky-integrator folded constants: v_n = v*(1-1/tau) + nom*(1/tau)
#define OM_TO   (1.0f - 1.0f / T_O)
#define OM_TSN  (1.0f - 1.0f / T_SN)
#define OM_TSP  (1.0f - 1.0f / T_SP)
#define RO_TO   (RO_C / T_O)

// Degree-13 polynomial coefficients for ve_sum (tx = (1-m^2)/2 identity)
#define A0d (-31593.7)
#define A1d (0.106747)
#define A2d (24606.4)
#define A3d (-78561.9)
#define A4d (13317.9)
#define A5d (307387.0)
#define A6d (84916.1)
#define A7d (-1074690.0)
#define A8d (2285.04)
#define A9d (990894.0)
#define A10d (283920.0)
#define A11d (-161513.0)
#define A12d (-469218.0)
#define Fd  (96487.0)

#define PC0  ((float)((-0.5 * A1d) / Fd))
#define PC1  ((float)((A0d - A2d) / Fd))
#define PC2  ((float)((1.5 * (A1d - A3d)) / Fd))
#define PC3  ((float)((2.0 * (A2d - A4d)) / Fd))
#define PC4  ((float)((2.5 * (A3d - A5d)) / Fd))
#define PC5  ((float)((3.0 * (A4d - A6d)) / Fd))
#define PC6  ((float)((3.5 * (A5d - A7d)) / Fd))
#define PC7  ((float)((4.0 * (A6d - A8d)) / Fd))
#define PC8  ((float)((4.5 * (A7d - A9d)) / Fd))
#define PC9  ((float)((5.0 * (A8d - A10d)) / Fd))
#define PC10 ((float)((5.5 * (A9d - A11d)) / Fd))
#define PC11 ((float)((6.0 * (A10d - A12d)) / Fd))
#define PC12 ((float)((6.5 * A11d) / Fd))
#define PC13 ((float)((7.0 * A12d) / Fd))

// Estrin evaluation of the degree-13 polynomial in m = 2x-1.
__device__ __forceinline__ float ve_sum_p_poly(float m) {
    float m2 = m * m;
    float m4 = m2 * m2;
    float m8 = m4 * m4;
    float e0 = fmaf(PC1,  m, PC0);
    float e1 = fmaf(PC3,  m, PC2);
    float e2 = fmaf(PC5,  m, PC4);
    float e3 = fmaf(PC7,  m, PC6);
    float e4 = fmaf(PC9,  m, PC8);
    float e5 = fmaf(PC11, m, PC10);
    float e6 = fmaf(PC13, m, PC12);
    float f0 = fmaf(e1, m2, e0);
    float f1 = fmaf(e3, m2, e2);
    float f2 = fmaf(e5, m2, e4);
    float g0 = fmaf(f1, m4, f0);
    float g1 = fmaf(e6, m4, f2);
    return fmaf(g1, m8, g0);
}

// log2(y + sqrt(y^2+1)) for y > 0; sqrt via v*rsqrt(v), no refinement
__device__ __forceinline__ float asinh_log2_pos(float y) {
    float v = fmaf(y, y, 1.0f);
    float s = v * rsqrtf(v);
    return __log2f(y + s);
}

// 256-bit non-coherent vector load (read-only data) + 256-bit store
__device__ __forceinline__ void ldg256_nc(const float* p, float r[8]) {
    asm volatile("ld.global.nc.v8.f32 {%0,%1,%2,%3,%4,%5,%6,%7}, [%8];"
                 : "=f"(r[0]), "=f"(r[1]), "=f"(r[2]), "=f"(r[3]),
                   "=f"(r[4]), "=f"(r[5]), "=f"(r[6]), "=f"(r[7])
                 : "l"(p));
}
__device__ __forceinline__ void stg256(float* p, const float r[8]) {
    asm volatile("st.global.v8.f32 [%0], {%1,%2,%3,%4,%5,%6,%7,%8};"
                 :: "l"(p),
                    "f"(r[0]), "f"(r[1]), "f"(r[2]), "f"(r[3]),
                    "f"(r[4]), "f"(r[5]), "f"(r[6]), "f"(r[7])
                 : "memory");
}

__global__ void __launch_bounds__(512)
battery_cell_kernel(const float* __restrict__ inp,
                    const float* __restrict__ states,
                    float* __restrict__ out, int B)
{
    int t = blockIdx.x * blockDim.x + threadIdx.x;
    if (t >= B) return;

    // Widest-latency load first, then scalar input.
    float s[8];
    ldg256_nc(states + 8LL * t, s);   // one LDG.E.256 (non-coherent path)
    float i = __ldg(inp + t);

    float Tb = s[0], Vo = s[1], Vsn = s[2], Vsp = s[3];
    float qnB = s[4], qnS = s[5], qpB = s[6], qpS = s[7];

    float xnS = qnS * INV_QSMAX;
    float xpS = qpS * INV_QSMAX;

    float qdDn = (qnB * INV_VOLB - qnS * INV_VOLS) * INV_TDIFF;
    float qdDp = (qpB * INV_VOLB - qpS * INV_VOLS) * INV_TDIFF;

    float argN = i * CN_C * rsqrtf(xnS * (1.0f - xnS));
    float argP = i * CP_C * rsqrtf(xpS * (1.0f - xpS));

    float rtfa   = RTFA_LN2 * Tb;
    float VsnNom = rtfa * asinh_log2_pos(argN);
    float VspNom = rtfa * asinh_log2_pos(argP);

    float Vo_n  = fmaf(i, RO_TO, Vo * OM_TO);
    float Vsn_n = fmaf(VsnNom, INV_TSN, Vsn * OM_TSN);
    float Vsp_n = fmaf(VspNom, INV_TSP, Vsp * OM_TSP);
    float qnB_n = qnB - qdDn;
    float qnS_n = qnS + (qdDn - i);
    float qpB_n = qpB - qdDp;
    float qpS_n = qpS + (i + qdDp);

    float xnS2 = qnS_n * INV_QSMAX;
    float xpS2 = qpS_n * INV_QSMAX;

    float rtf = RTF_LN2 * Tb;
    float lgN = __log2f(1.0f - xnS2) - __log2f(xnS2);
    float lgP = __log2f(1.0f - xpS2) - __log2f(xpS2);
    float mN  = 2.0f * xnS2 - 1.0f;
    float mP  = 2.0f * xpS2 - 1.0f;
    float Ven = U0N + rtf * lgN + AN0_F * mN;
    float Vep = U0P + rtf * lgP + ve_sum_p_poly(mP);

    float V = Vep - Ven - Vo_n - Vsn_n - Vsp_n;

    reinterpret_cast<float2*>(out)[t] = make_float2(Tb - 273.15f, V);

    float xo[8] = {Tb, Vo_n, Vsn_n, Vsp_n, qnB_n, qnS_n, qpB_n, qpS_n};
    stg256(out + 2LL * B + 8LL * t, xo);
}

extern "C" void kernel_launch(void* const* d_in, const int* in_sizes, int n_in,
                              void* d_out, int out_size)
{
    const float* inp    = (const float*)d_in[0];   // (B,1)
    const float* states = (const float*)d_in[1];   // (B,8)
    int B = in_sizes[0];
    float* out = (float*)d_out;                    // Z (B,2) ++ X_next (B,8)

    int threads = 512;
    int blocks = (B + threads - 1) / threads;
    battery_cell_kernel<<<blocks, threads>>>(inp, states, out, B);
}

// round 13
// speedup vs baseline: 1.0311x; 1.0311x over previous
#include <cuda_runtime.h>

#define R_GAS   8.3144621f
#define F_CONST 96487.0f
#define ALPHA   0.5f
#define SN_C    0.000437545f
#define SP_C    0.00030962f
#define KN_C    2120.96f
#define KP_C    248898.0f
#define RO_C    0.117215f
#define T_O     6.08671f
#define T_SN    1001.38f
#define T_SP    46.4311f
#define U0P     4.03f
#define U0N     0.01f
#define Q_MAX   (7600.0f / 0.6f)
#define VOL     2e-05f
#define VOL_S   (0.1f * VOL)
#define VOL_B   (VOL - VOL_S)
#define Q_S_MAX (Q_MAX * VOL_S / VOL)
#define LN2_F   0.69314718055994531f

#define INV_QSMAX  (1.0f / Q_S_MAX)
#define INV_VOLB   (1.0f / VOL_B)
#define INV_VOLS   (1.0f / VOL_S)
#define T_DIFF_    7000000.0f
#define INV_TDIFF  (1.0f / T_DIFF_)
#define INV_TSN    (1.0f / T_SN)
#define INV_TSP    (1.0f / T_SP)
#define RTF_LN2    (R_GAS / F_CONST * LN2_F)
#define RTFA_LN2   (R_GAS / F_CONST / ALPHA * LN2_F)
#define CN_C       (1.0f / (SN_C * 2.0f * KN_C))
#define CP_C       (1.0f / (SP_C * 2.0f * KP_C))
#define AN0_F      (86.19f / F_CONST)

// Leaky-integrator folded constants: v_n = v*(1-1/tau) + nom*(1/tau)
#define OM_TO   (1.0f - 1.0f / T_O)
#define OM_TSN  (1.0f - 1.0f / T_SN)
#define OM_TSP  (1.0f - 1.0f / T_SP)
#define RO_TO   (RO_C / T_O)

// Degree-13 polynomial coefficients for ve_sum (tx = (1-m^2)/2 identity)
#define A0d (-31593.7)
#define A1d (0.106747)
#define A2d (24606.4)
#define A3d (-78561.9)
#define A4d (13317.9)
#define A5d (307387.0)
#define A6d (84916.1)
#define A7d (-1074690.0)
#define A8d (2285.04)
#define A9d (990894.0)
#define A10d (283920.0)
#define A11d (-161513.0)
#define A12d (-469218.0)
#define Fd  (96487.0)

#define PC0  ((float)((-0.5 * A1d) / Fd))
#define PC1  ((float)((A0d - A2d) / Fd))
#define PC2  ((float)((1.5 * (A1d - A3d)) / Fd))
#define PC3  ((float)((2.0 * (A2d - A4d)) / Fd))
#define PC4  ((float)((2.5 * (A3d - A5d)) / Fd))
#define PC5  ((float)((3.0 * (A4d - A6d)) / Fd))
#define PC6  ((float)((3.5 * (A5d - A7d)) / Fd))
#define PC7  ((float)((4.0 * (A6d - A8d)) / Fd))
#define PC8  ((float)((4.5 * (A7d - A9d)) / Fd))
#define PC9  ((float)((5.0 * (A8d - A10d)) / Fd))
#define PC10 ((float)((5.5 * (A9d - A11d)) / Fd))
#define PC11 ((float)((6.0 * (A10d - A12d)) / Fd))
#define PC12 ((float)((6.5 * A11d) / Fd))
#define PC13 ((float)((7.0 * A12d) / Fd))

// Estrin evaluation of the degree-13 polynomial in m = 2x-1.
__device__ __forceinline__ float ve_sum_p_poly(float m) {
    float m2 = m * m;
    float m4 = m2 * m2;
    float m8 = m4 * m4;
    float e0 = fmaf(PC1,  m, PC0);
    float e1 = fmaf(PC3,  m, PC2);
    float e2 = fmaf(PC5,  m, PC4);
    float e3 = fmaf(PC7,  m, PC6);
    float e4 = fmaf(PC9,  m, PC8);
    float e5 = fmaf(PC11, m, PC10);
    float e6 = fmaf(PC13, m, PC12);
    float f0 = fmaf(e1, m2, e0);
    float f1 = fmaf(e3, m2, e2);
    float f2 = fmaf(e5, m2, e4);
    float g0 = fmaf(f1, m4, f0);
    float g1 = fmaf(e6, m4, f2);
    return fmaf(g1, m8, g0);
}

// log2(y + sqrt(y^2+1)) for y > 0; sqrt via v*rsqrt(v), no refinement
__device__ __forceinline__ float asinh_log2_pos(float y) {
    float v = fmaf(y, y, 1.0f);
    float s = v * rsqrtf(v);
    return __log2f(y + s);
}

// 256-bit vector load/store (sm_103a: LDG.E.256 / STG.E.256)
__device__ __forceinline__ void ldg256(const float* p, float r[8]) {
    asm volatile("ld.global.v8.f32 {%0,%1,%2,%3,%4,%5,%6,%7}, [%8];"
                 : "=f"(r[0]), "=f"(r[1]), "=f"(r[2]), "=f"(r[3]),
                   "=f"(r[4]), "=f"(r[5]), "=f"(r[6]), "=f"(r[7])
                 : "l"(p));
}
__device__ __forceinline__ void stg256(float* p, const float r[8]) {
    asm volatile("st.global.v8.f32 [%0], {%1,%2,%3,%4,%5,%6,%7,%8};"
                 :: "l"(p),
                    "f"(r[0]), "f"(r[1]), "f"(r[2]), "f"(r[3]),
                    "f"(r[4]), "f"(r[5]), "f"(r[6]), "f"(r[7])
                 : "memory");
}

__global__ void __launch_bounds__(256)
battery_cell_kernel(const float* __restrict__ inp,
                    const float* __restrict__ states,
                    float* __restrict__ out, int B)
{
    int t = blockIdx.x * blockDim.x + threadIdx.x;
    if (t >= B) return;

    float i = inp[t];
    float s[8];
    ldg256(states + 8LL * t, s);   // one LDG.E.256: whole state row
    float Tb = s[0], Vo = s[1], Vsn = s[2], Vsp = s[3];
    float qnB = s[4], qnS = s[5], qpB = s[6], qpS = s[7];

    float xnS = qnS * INV_QSMAX;
    float xpS = qpS * INV_QSMAX;

    float qdDn = (qnB * INV_VOLB - qnS * INV_VOLS) * INV_TDIFF;
    float qdDp = (qpB * INV_VOLB - qpS * INV_VOLS) * INV_TDIFF;

    float argN = i * CN_C * rsqrtf(xnS * (1.0f - xnS));
    float argP = i * CP_C * rsqrtf(xpS * (1.0f - xpS));

    float rtfa   = RTFA_LN2 * Tb;
    float VsnNom = rtfa * asinh_log2_pos(argN);
    float VspNom = rtfa * asinh_log2_pos(argP);

    float Vo_n  = fmaf(i, RO_TO, Vo * OM_TO);
    float Vsn_n = fmaf(VsnNom, INV_TSN, Vsn * OM_TSN);
    float Vsp_n = fmaf(VspNom, INV_TSP, Vsp * OM_TSP);
    float qnB_n = qnB - qdDn;
    float qnS_n = qnS + (qdDn - i);
    float qpB_n = qpB - qdDp;
    float qpS_n = qpS + (i + qdDp);

    float xnS2 = qnS_n * INV_QSMAX;
    float xpS2 = qpS_n * INV_QSMAX;

    float rtf = RTF_LN2 * Tb;
    float lgN = __log2f(1.0f - xnS2) - __log2f(xnS2);
    float lgP = __log2f(1.0f - xpS2) - __log2f(xpS2);
    float mN  = 2.0f * xnS2 - 1.0f;
    float mP  = 2.0f * xpS2 - 1.0f;
    float Ven = U0N + rtf * lgN + AN0_F * mN;
    float Vep = U0P + rtf * lgP + ve_sum_p_poly(mP);

    float V = Vep - Ven - Vo_n - Vsn_n - Vsp_n;

    reinterpret_cast<float2*>(out)[t] = make_float2(Tb - 273.15f, V);

    float xo[8] = {Tb, Vo_n, Vsn_n, Vsp_n, qnB_n, qnS_n, qpB_n, qpS_n};
    stg256(out + 2LL * B + 8LL * t, xo);
}

extern "C" void kernel_launch(void* const* d_in, const int* in_sizes, int n_in,
                              void* d_out, int out_size)
{
    const float* inp    = (const float*)d_in[0];   // (B,1)
    const float* states = (const float*)d_in[1];   // (B,8)
    int B = in_sizes[0];
    float* out = (float*)d_out;                    // Z (B,2) ++ X_next (B,8)

    int threads = 256;
    int blocks = (B + threads - 1) / threads;
    battery_cell_kernel<<<blocks, threads>>>(inp, states, out, B);
}